// round 9
// baseline (speedup 1.0000x reference)
#include <cuda_runtime.h>
#include <cstdint>
#include <float.h>
#include <math.h>

#define B   64
#define Q   32
#define KD  100
#define QK  (Q*KD)             // 3200
#define BQ  (B*Q)              // 2048 rows (i,q)
#define ROWLEN  (B*KD)         // 6400 elems per softmax row
#define ROWLEN4 (ROWLEN/4)     // 1600 float4
#define TEMP 0.07f
#define EMA  0.99f
#define NCONF_ROWS 30000
#define ROWF4 (QK/4)           // 800 float4 per confidence row

#define N_OUT   ((size_t)B*B*Q*KD)          // 13107200
#define N_CONF  ((size_t)NCONF_ROWS*QK)     // 96000000
#define N_MASK  ((size_t)B*Q*KD)            // 204800

#define NCOPY 2048
#define GRID  (BQ + NCOPY)                  // 4096, parity-interleaved

__device__ int      g_bidx[B];
__device__ int      g_is_last[B];
__device__ int      g_mask_w;     // 1=u8, 4=i32, 8=i64, 5=f32, 9=f64
__device__ int      g_topk;
__device__ unsigned g_bitmap[(NCONF_ROWS + 31) / 32];
__device__ float    g_loss_num;
__device__ float    g_phrase_cnt;
__device__ int      g_done;

__device__ __forceinline__ bool mask_at(const unsigned char* xm, size_t idx, int w) {
    if (w == 1) return xm[idx] != 0;
    if (w == 4) return ((const int*)xm)[idx] != 0;
    if (w == 8) return ((const long long*)xm)[idx] != 0;
    if (w == 5) return ((const float*)xm)[idx] != 0.f;
    return ((const double*)xm)[idx] != 0.0;
}

// One-block setup: accumulator reset, dtype detection, batch_index decode,
// is_last flags (duplicate scatter -> last occurrence wins), row bitmap.
__global__ void __launch_bounds__(256) k_pre(
        const unsigned char* __restrict__ xmask,
        const int* __restrict__ braw,
        const int* __restrict__ traw, int has_topk) {
    const int t = threadIdx.x;
    __shared__ int sb[B];

    if (t == 0) { g_loss_num = 0.f; g_phrase_cnt = 0.f; g_done = 0; }

    // ---- x_mask width (probe first 256 logical elements) ----
    bool v8 = true, v4 = true, vf = true, vd = true;
    {
        const unsigned char* p = xmask + 8 * (size_t)t;
        if (p[0] > 1) v8 = false;
        #pragma unroll
        for (int j = 1; j < 8; ++j) if (p[j] != 0) v8 = false;
        const unsigned char* q = xmask + 4 * (size_t)t;
        if (q[0] > 1 || q[1] != 0 || q[2] != 0 || q[3] != 0) v4 = false;
        float  f = ((const float*)xmask)[t];
        if (f != 0.f && f != 1.f) vf = false;
        double d = ((const double*)xmask)[t];
        if (d != 0.0 && d != 1.0) vd = false;
    }
    const bool ok8 = __syncthreads_and(v8);
    const bool ok4 = __syncthreads_and(v4);
    const bool okd = __syncthreads_and(vd);
    const bool okf = __syncthreads_and(vf);
    if (t == 0) g_mask_w = ok8 ? 8 : (ok4 ? 4 : (okd ? 9 : (okf ? 5 : 1)));

    // ---- batch_index dtype + decode ----
    bool b64 = true, b32 = true, bfl = true;
    if (t < B) {
        if (t < 32) {   // i64 probe stays within first 256 bytes
            if (braw[2*t+1] != 0 || braw[2*t] < 0 || braw[2*t] >= NCONF_ROWS) b64 = false;
        }
        if (braw[t] < 0 || braw[t] >= NCONF_ROWS) b32 = false;
        float f = ((const float*)braw)[t];
        if (!(f >= 0.f && f < (float)NCONF_ROWS) || f != floorf(f)) bfl = false;
    }
    const bool ok64 = __syncthreads_and(b64);
    const bool ok32 = __syncthreads_and(b32);
    const bool okbf = __syncthreads_and(bfl);
    if (t < B) {
        int v;
        if (ok64)      v = (int)((const long long*)braw)[t];
        else if (ok32) v = braw[t];
        else if (okbf) v = (int)((const float*)braw)[t];
        else           v = (int)((const double*)braw)[t];
        g_bidx[t] = v;
        sb[t] = v;
    }

    // ---- zero bitmap ----
    for (int w = t; w < (NCONF_ROWS + 31) / 32; w += 256) g_bitmap[w] = 0u;
    __syncthreads();

    // ---- is_last + bitmap bits ----
    if (t < B) {
        bool last = true;
        for (int j = t + 1; j < B; ++j) if (sb[j] == sb[t]) { last = false; break; }
        g_is_last[t] = last ? 1 : 0;
        const int n = sb[t];
        atomicOr(&g_bitmap[n >> 5], 1u << (n & 31));
    }

    // ---- topk ----
    if (t == 0) {
        int v = 3;
        if (has_topk) {
            int vi = traw[0];
            if (vi >= 1 && vi <= KD) v = vi;
            else {
                float vfv = ((const float*)traw)[0];
                if (vfv >= 1.f && vfv <= (float)KD) v = (int)vfv;
                else {
                    double vd2 = ((const double*)traw)[0];
                    if (vd2 >= 1.0 && vd2 <= (double)KD) v = (int)vd2;
                }
            }
        }
        if (v > KD) v = KD;
        if (v < 0)  v = 0;
        g_topk = v;
    }
}

// Heterogeneous grid: odd blocks stream the conf->new_conf copy with
// 16B-aligned destination stores (dest base is +1 float off source alignment:
// aligned dest f4 = {src[a].w, src[a+1].xyz}); even blocks do the per-(i,q)
// softmax + row work with the same aligned-store trick for atten.
__global__ void __launch_bounds__(256) k_main(
        const float* __restrict__ outp,
        const float* __restrict__ confid,
        const unsigned char* __restrict__ xmask,
        float* __restrict__ atten,
        float* __restrict__ logit_m_o,
        float* __restrict__ pseudo_o,
        float* __restrict__ conf_o,
        float* __restrict__ newc,
        float* __restrict__ out) {
    const int bid = blockIdx.x;
    const int t = threadIdx.x;           // 0..255
    __shared__ __align__(16) float sv[ROWLEN];
    __shared__ float red[256];
    __shared__ int   ri[256];
    __shared__ float spseudo[KD];
    __shared__ unsigned char ssel[KD];

    if (bid & 1) {
        // ================= COPY BLOCK =================
        const int c = bid >> 1;                       // 0..2047
        const float4* c4 = (const float4*)confid;     // source 16B-aligned
        const size_t totalv = N_CONF / 4;             // 24,000,000 f4
        const size_t per = (totalv + NCOPY - 1) / NCOPY;
        size_t vr = (size_t)c * per;
        const size_t v1 = (vr + per < totalv) ? vr + per : totalv;

        while (vr < v1) {
            const int n = (int)(vr / ROWF4);          // once per row segment
            size_t rend = (size_t)(n + 1) * ROWF4;
            if (rend > v1) rend = v1;
            if (!((g_bitmap[n >> 5] >> (n & 31)) & 1u)) {
                const size_t sbase = (size_t)n * ROWF4;   // f4 idx of row start
                const size_t fbase = (size_t)n * QK;      // float idx of row start
                const int lo = (int)(vr - sbase), hi = (int)(rend - sbase);
                // aligned-dest groups: g in [lo, hi-2]; dest floats [4g+3, 4g+7)
                for (int g = lo + t; g <= hi - 2; g += 256) {
                    float4 a = c4[sbase + g];
                    float4 b = c4[sbase + g + 1];
                    float4 o = make_float4(a.w, b.x, b.y, b.z);
                    __stcs((float4*)(newc + fbase + 3 + 4 * (size_t)g), o);
                }
                // boundary scalars: floats {4lo,4lo+1,4lo+2, 4hi-1} of this row
                if (t < 4) {
                    const int fi = (t < 3) ? (4 * lo + t) : (4 * hi - 1);
                    __stcs(&newc[fbase + fi], confid[fbase + fi]);
                }
            }
            vr = rend;
        }
        __syncthreads();
        if (t == 0 && atomicAdd(&g_done, 1) == GRID - 1) {
            const float ln = atomicAdd(&g_loss_num, 0.f);
            const float pc = atomicAdd(&g_phrase_cnt, 0.f);
            out[0] = ln / (pc + 1.1920929e-07f);    // BASE_TEMPERATURE = 1
        }
        return;
    }

    // ================= ROW BLOCK =================
    const int r = bid >> 1;              // 0..2047
    const int i = r / Q, qq = r % Q;
    const size_t base = (size_t)i * B * QK + (size_t)qq * KD;
    const int mask_w = g_mask_w;
    const int kk_top = g_topk;
    const int bi     = g_bidx[i];

    // ---- load + scale + max ----
    float mx = -FLT_MAX;
    for (int f = t; f < ROWLEN4; f += 256) {
        const int e  = 4 * f;
        const int j  = e / KD;
        const int kk = e % KD;          // KD%4==0 -> all 4 lanes same j, contiguous
        float4 v = *(const float4*)(outp + base + (size_t)j * QK + kk);
        v.x *= (1.f/TEMP); v.y *= (1.f/TEMP); v.z *= (1.f/TEMP); v.w *= (1.f/TEMP);
        *(float4*)(sv + e) = v;
        mx = fmaxf(mx, fmaxf(fmaxf(v.x, v.y), fmaxf(v.z, v.w)));
    }
    red[t] = mx; __syncthreads();
    for (int s = 128; s > 0; s >>= 1) { if (t < s) red[t] = fmaxf(red[t], red[t+s]); __syncthreads(); }
    mx = red[0]; __syncthreads();

    float sum = 0.f;
    for (int e = t; e < ROWLEN; e += 256) sum += __expf(sv[e] - mx);
    red[t] = sum; __syncthreads();
    for (int s = 128; s > 0; s >>= 1) { if (t < s) red[t] += red[t+s]; __syncthreads(); }
    const float logZ = mx + __logf(red[0]);
    __syncthreads();

    // ---- atten store, 16B-aligned dest (atten = out+1, so float idx ≡3 mod 4
    //      is aligned): per 100-float segment, 24 vec groups + 4 scalars ----
    {
        const float4* sv4 = (const float4*)sv;
        for (int f = t; f < 64 * 24; f += 256) {
            const int j = f / 24;            // segment (0..63)
            const int u = f - j * 24;        // group within segment (0..23)
            float4 a = sv4[j * 25 + u];      // floats j*100+4u .. +3
            float4 b = sv4[j * 25 + u + 1];
            float4 o = make_float4(a.w - logZ, b.x - logZ, b.y - logZ, b.z - logZ);
            __stcs((float4*)(atten + base + (size_t)j * QK + 3 + 4 * u), o);
        }
        // leftovers kk in {0,1,2,99}: 64 segments * 4 = 256 = blockDim
        const int j = t >> 2, w = t & 3;
        const int kk = (w < 3) ? w : 99;
        __stcs(&atten[base + (size_t)j * QK + kk], sv[j * KD + kk] - logZ);
    }

    // ---- per-row work: diagonal slice is in smem at sv[i*KD + k] ----
    const size_t rowo = ((size_t)i * Q + qq) * KD;
    const size_t crow = ((size_t)bi * Q + qq) * KD;

    bool  m    = false;
    float lg   = -FLT_MAX;
    float rawc = 0.f;
    float lgt  = 0.f;
    if (t < KD) {
        m    = mask_at(xmask, rowo + t, mask_w);
        lgt  = sv[i*KD + t] - logZ;
        lg   = m ? lgt : -FLT_MAX;
        logit_m_o[rowo + t] = lg;
        rawc = confid[crow + t];
        spseudo[t] = m ? rawc : 0.f;
        ssel[t] = 0;
    }
    __syncthreads();

    // iterative top-k (k small); tie -> lower index (jax.lax.top_k order)
    for (int it = 0; it < kk_top; ++it) {
        float v = (t < KD && !ssel[t]) ? spseudo[t] : -FLT_MAX;
        red[t] = v; ri[t] = t;
        __syncthreads();
        for (int s = 128; s > 0; s >>= 1) {
            if (t < s) {
                if (red[t+s] > red[t] || (red[t+s] == red[t] && ri[t+s] < ri[t])) {
                    red[t] = red[t+s]; ri[t] = ri[t+s];
                }
            }
            __syncthreads();
        }
        if (t == 0) ssel[ri[0]] = 1;
        __syncthreads();
    }

    // masked pseudo + loss contribution
    float contrib = 0.f;
    bool  sel = false;
    if (t < KD) {
        sel = (ssel[t] != 0) && m;
        const float pv = sel ? spseudo[t] : 0.f;
        pseudo_o[rowo + t] = pv;
        contrib = -pv * lgt;
    }
    red[t] = contrib; __syncthreads();
    for (int s = 128; s > 0; s >>= 1) { if (t < s) red[t] += red[t+s]; __syncthreads(); }
    if (t == 0) {
        atomicAdd(&g_loss_num, red[0]);
        if (sel) atomicAdd(&g_phrase_cnt, 1.f);   // thread 0 holds k==0
    }
    __syncthreads();

    // conf = softmax(logit_m), zero where masked; argmax (tie -> lower idx)
    red[t] = lg; __syncthreads();
    for (int s = 128; s > 0; s >>= 1) { if (t < s) red[t] = fmaxf(red[t], red[t+s]); __syncthreads(); }
    const float mmax = red[0]; __syncthreads();
    float ev = (t < KD && lg > -FLT_MAX) ? __expf(lg - mmax) : 0.f;
    red[t] = ev; __syncthreads();
    for (int s = 128; s > 0; s >>= 1) { if (t < s) red[t] += red[t+s]; __syncthreads(); }
    const float denom = red[0]; __syncthreads();
    if (t < KD) conf_o[rowo + t] = m ? (ev / denom) : 0.f;

    red[t] = (t < KD && m) ? ev : -FLT_MAX; ri[t] = t;
    __syncthreads();
    for (int s = 128; s > 0; s >>= 1) {
        if (t < s) {
            if (red[t+s] > red[t] || (red[t+s] == red[t] && ri[t+s] < ri[t])) {
                red[t] = red[t+s]; ri[t] = ri[t+s];
            }
        }
        __syncthreads();
    }
    const int harg = ri[0];

    // ---- EMA rewrite of this block's scattered row (last occurrence wins;
    //      copy blocks skip these rows via bitmap -> no write race) ----
    if (g_is_last[i] && t < KD) {
        const float h = (t == harg && m) ? 1.f : 0.f;
        newc[crow + t] = EMA * rawc + (1.f - EMA) * h;
    }

    __syncthreads();
    if (t == 0 && atomicAdd(&g_done, 1) == GRID - 1) {
        const float ln = atomicAdd(&g_loss_num, 0.f);
        const float pc = atomicAdd(&g_phrase_cnt, 0.f);
        out[0] = ln / (pc + 1.1920929e-07f);
    }
}

extern "C" void kernel_launch(void* const* d_in, const int* in_sizes, int n_in,
                              void* d_out, int out_size) {
    // Bind inputs by element count (all sizes distinct) -> order-proof.
    const float* outp = nullptr;
    const float* confid = nullptr;
    const int*   braw = nullptr;
    const unsigned char* xmask = nullptr;
    const int*   topkp = nullptr;
    for (int idx = 0; idx < n_in; ++idx) {
        const size_t sz = (size_t)in_sizes[idx];
        if      (sz == N_OUT)  outp   = (const float*)d_in[idx];
        else if (sz == N_CONF) confid = (const float*)d_in[idx];
        else if (sz == (size_t)B) braw = (const int*)d_in[idx];
        else if (sz == N_MASK) xmask  = (const unsigned char*)d_in[idx];
        else if (sz == 1)      topkp  = (const int*)d_in[idx];
    }
    float* out = (float*)d_out;

    const size_t ATT = 1;
    const size_t LOG = ATT + N_OUT;
    const size_t PSE = LOG + N_MASK;
    const size_t CNF = PSE + N_MASK;
    const size_t NEW = CNF + N_MASK;

    k_pre<<<1, 256>>>(xmask, braw, topkp, topkp ? 1 : 0);
    k_main<<<GRID, 256>>>(outp, confid, xmask,
                          out + ATT, out + LOG, out + PSE, out + CNF, out + NEW,
                          out);
}

// round 10
// speedup vs baseline: 1.1750x; 1.1750x over previous
#include <cuda_runtime.h>
#include <cstdint>
#include <float.h>
#include <math.h>

#define B   64
#define Q   32
#define KD  100
#define QK  (Q*KD)             // 3200
#define BQ  (B*Q)              // 2048 rows (i,q)
#define ROWLEN  (B*KD)         // 6400 elems per softmax row
#define ROWLEN4 (ROWLEN/4)     // 1600 float4
#define TEMP 0.07f
#define EMA  0.99f
#define NCONF_ROWS 30000
#define ROWF4 (QK/4)           // 800 float4 per confidence row

#define N_OUT   ((size_t)B*B*Q*KD)          // 13107200
#define N_CONF  ((size_t)NCONF_ROWS*QK)     // 96000000
#define N_MASK  ((size_t)B*Q*KD)            // 204800

#define NCOPY 2048
#define GRID  (BQ + NCOPY)                  // 4096, parity-interleaved

__device__ int      g_bidx[B];
__device__ int      g_is_last[B];
__device__ int      g_mask_w;     // 1=u8, 4=i32, 8=i64, 5=f32, 9=f64
__device__ int      g_topk;
__device__ unsigned g_bitmap[(NCONF_ROWS + 31) / 32];
__device__ float    g_loss_num;
__device__ float    g_phrase_cnt;
__device__ int      g_done;

__device__ __forceinline__ bool mask_at(const unsigned char* xm, size_t idx, int w) {
    if (w == 1) return xm[idx] != 0;
    if (w == 4) return ((const int*)xm)[idx] != 0;
    if (w == 8) return ((const long long*)xm)[idx] != 0;
    if (w == 5) return ((const float*)xm)[idx] != 0.f;
    return ((const double*)xm)[idx] != 0.0;
}

// One-block setup: accumulator reset, dtype detection, batch_index decode,
// is_last flags (duplicate scatter -> last occurrence wins), row bitmap.
__global__ void __launch_bounds__(256) k_pre(
        const unsigned char* __restrict__ xmask,
        const int* __restrict__ braw,
        const int* __restrict__ traw, int has_topk) {
    const int t = threadIdx.x;
    __shared__ int sb[B];

    if (t == 0) { g_loss_num = 0.f; g_phrase_cnt = 0.f; g_done = 0; }

    // ---- x_mask width (probe first 256 logical elements) ----
    bool v8 = true, v4 = true, vf = true, vd = true;
    {
        const unsigned char* p = xmask + 8 * (size_t)t;
        if (p[0] > 1) v8 = false;
        #pragma unroll
        for (int j = 1; j < 8; ++j) if (p[j] != 0) v8 = false;
        const unsigned char* q = xmask + 4 * (size_t)t;
        if (q[0] > 1 || q[1] != 0 || q[2] != 0 || q[3] != 0) v4 = false;
        float  f = ((const float*)xmask)[t];
        if (f != 0.f && f != 1.f) vf = false;
        double d = ((const double*)xmask)[t];
        if (d != 0.0 && d != 1.0) vd = false;
    }
    const bool ok8 = __syncthreads_and(v8);
    const bool ok4 = __syncthreads_and(v4);
    const bool okd = __syncthreads_and(vd);
    const bool okf = __syncthreads_and(vf);
    if (t == 0) g_mask_w = ok8 ? 8 : (ok4 ? 4 : (okd ? 9 : (okf ? 5 : 1)));

    // ---- batch_index dtype + decode ----
    bool b64 = true, b32 = true, bfl = true;
    if (t < B) {
        if (t < 32) {   // i64 probe stays within first 256 bytes
            if (braw[2*t+1] != 0 || braw[2*t] < 0 || braw[2*t] >= NCONF_ROWS) b64 = false;
        }
        if (braw[t] < 0 || braw[t] >= NCONF_ROWS) b32 = false;
        float f = ((const float*)braw)[t];
        if (!(f >= 0.f && f < (float)NCONF_ROWS) || f != floorf(f)) bfl = false;
    }
    const bool ok64 = __syncthreads_and(b64);
    const bool ok32 = __syncthreads_and(b32);
    const bool okbf = __syncthreads_and(bfl);
    if (t < B) {
        int v;
        if (ok64)      v = (int)((const long long*)braw)[t];
        else if (ok32) v = braw[t];
        else if (okbf) v = (int)((const float*)braw)[t];
        else           v = (int)((const double*)braw)[t];
        g_bidx[t] = v;
        sb[t] = v;
    }

    // ---- zero bitmap ----
    for (int w = t; w < (NCONF_ROWS + 31) / 32; w += 256) g_bitmap[w] = 0u;
    __syncthreads();

    // ---- is_last + bitmap bits ----
    if (t < B) {
        bool last = true;
        for (int j = t + 1; j < B; ++j) if (sb[j] == sb[t]) { last = false; break; }
        g_is_last[t] = last ? 1 : 0;
        const int n = sb[t];
        atomicOr(&g_bitmap[n >> 5], 1u << (n & 31));
    }

    // ---- topk ----
    if (t == 0) {
        int v = 3;
        if (has_topk) {
            int vi = traw[0];
            if (vi >= 1 && vi <= KD) v = vi;
            else {
                float vfv = ((const float*)traw)[0];
                if (vfv >= 1.f && vfv <= (float)KD) v = (int)vfv;
                else {
                    double vd2 = ((const double*)traw)[0];
                    if (vd2 >= 1.0 && vd2 <= (double)KD) v = (int)vd2;
                }
            }
        }
        if (v > KD) v = KD;
        if (v < 0)  v = 0;
        g_topk = v;
    }
}

__device__ __forceinline__ void copy_elem(float* __restrict__ newc,
                                          unsigned v, float4 x) {
    const unsigned n = v / ROWF4;                 // confidence row
    if (!((g_bitmap[n >> 5] >> (n & 31)) & 1u)) {
        const size_t o = 4 * (size_t)v;
        __stcs(&newc[o + 0], x.x);
        __stcs(&newc[o + 1], x.y);
        __stcs(&newc[o + 2], x.z);
        __stcs(&newc[o + 3], x.w);
    }
}

// Heterogeneous grid: odd blocks stream the conf->new_conf copy (skipping
// scattered rows via bitmap, MLP-4 unrolled); even blocks do the per-(i,q)
// softmax + row work including the EMA rewrite of their own scattered row.
__global__ void __launch_bounds__(256) k_main(
        const float* __restrict__ outp,
        const float* __restrict__ confid,
        const unsigned char* __restrict__ xmask,
        float* __restrict__ atten,
        float* __restrict__ logit_m_o,
        float* __restrict__ pseudo_o,
        float* __restrict__ conf_o,
        float* __restrict__ newc,
        float* __restrict__ out) {
    const int bid = blockIdx.x;
    const int t = threadIdx.x;           // 0..255
    __shared__ __align__(16) float sv[ROWLEN];
    __shared__ float red[256];
    __shared__ int   ri[256];
    __shared__ float spseudo[KD];
    __shared__ unsigned char ssel[KD];

    if (bid & 1) {
        // ================= COPY BLOCK =================
        const unsigned c = (unsigned)(bid >> 1);
        const float4* c4 = (const float4*)confid;     // source 16B-aligned
        const unsigned nvec = (unsigned)(N_CONF / 4); // 24,000,000 (fits u32)
        const unsigned stride = NCOPY * 256;
        unsigned v = c * 256 + t;
        // 4 independent in-flight loads per iteration (MLP=4)
        for (; v + 3u * stride < nvec; v += 4u * stride) {
            float4 x0 = __ldcs(&c4[v]);
            float4 x1 = __ldcs(&c4[v + stride]);
            float4 x2 = __ldcs(&c4[v + 2u * stride]);
            float4 x3 = __ldcs(&c4[v + 3u * stride]);
            copy_elem(newc, v,               x0);
            copy_elem(newc, v + stride,      x1);
            copy_elem(newc, v + 2u * stride, x2);
            copy_elem(newc, v + 3u * stride, x3);
        }
        for (; v < nvec; v += stride) copy_elem(newc, v, __ldcs(&c4[v]));

        __syncthreads();
        if (t == 0 && atomicAdd(&g_done, 1) == GRID - 1) {
            const float ln = atomicAdd(&g_loss_num, 0.f);
            const float pc = atomicAdd(&g_phrase_cnt, 0.f);
            out[0] = ln / (pc + 1.1920929e-07f);    // BASE_TEMPERATURE = 1
        }
        return;
    }

    // ================= ROW BLOCK =================
    const int r = bid >> 1;              // 0..2047
    const int i = r / Q, qq = r % Q;
    const size_t base = (size_t)i * B * QK + (size_t)qq * KD;
    const int mask_w = g_mask_w;
    const int kk_top = g_topk;
    const int bi     = g_bidx[i];

    // ---- load (streaming, read-once) + scale + max ----
    float mx = -FLT_MAX;
    for (int f = t; f < ROWLEN4; f += 256) {
        const int e  = 4 * f;
        const int j  = e / KD;
        const int kk = e % KD;          // KD%4==0 -> all 4 lanes same j, contiguous
        float4 v = __ldcs((const float4*)(outp + base + (size_t)j * QK + kk));
        v.x *= (1.f/TEMP); v.y *= (1.f/TEMP); v.z *= (1.f/TEMP); v.w *= (1.f/TEMP);
        *(float4*)(sv + e) = v;
        mx = fmaxf(mx, fmaxf(fmaxf(v.x, v.y), fmaxf(v.z, v.w)));
    }
    red[t] = mx; __syncthreads();
    for (int s = 128; s > 0; s >>= 1) { if (t < s) red[t] = fmaxf(red[t], red[t+s]); __syncthreads(); }
    mx = red[0]; __syncthreads();

    float sum = 0.f;
    for (int e = t; e < ROWLEN; e += 256) sum += __expf(sv[e] - mx);
    red[t] = sum; __syncthreads();
    for (int s = 128; s > 0; s >>= 1) { if (t < s) red[t] += red[t+s]; __syncthreads(); }
    const float logZ = mx + __logf(red[0]);
    __syncthreads();

    // ---- atten store (scalar coalesced streaming; base 4B-aligned only) ----
    for (int e = t; e < ROWLEN; e += 256) {
        const int j  = e / KD;
        const int kk = e % KD;
        __stcs(&atten[base + (size_t)j * QK + kk], sv[e] - logZ);
    }

    // ---- per-row work: diagonal slice is in smem at sv[i*KD + k] ----
    const size_t rowo = ((size_t)i * Q + qq) * KD;
    const size_t crow = ((size_t)bi * Q + qq) * KD;

    bool  m    = false;
    float lg   = -FLT_MAX;
    float rawc = 0.f;
    float lgt  = 0.f;
    if (t < KD) {
        m    = mask_at(xmask, rowo + t, mask_w);
        lgt  = sv[i*KD + t] - logZ;
        lg   = m ? lgt : -FLT_MAX;
        logit_m_o[rowo + t] = lg;
        rawc = confid[crow + t];
        spseudo[t] = m ? rawc : 0.f;
        ssel[t] = 0;
    }
    __syncthreads();

    // iterative top-k (k small); tie -> lower index (jax.lax.top_k order)
    for (int it = 0; it < kk_top; ++it) {
        float v = (t < KD && !ssel[t]) ? spseudo[t] : -FLT_MAX;
        red[t] = v; ri[t] = t;
        __syncthreads();
        for (int s = 128; s > 0; s >>= 1) {
            if (t < s) {
                if (red[t+s] > red[t] || (red[t+s] == red[t] && ri[t+s] < ri[t])) {
                    red[t] = red[t+s]; ri[t] = ri[t+s];
                }
            }
            __syncthreads();
        }
        if (t == 0) ssel[ri[0]] = 1;
        __syncthreads();
    }

    // masked pseudo + loss contribution
    float contrib = 0.f;
    bool  sel = false;
    if (t < KD) {
        sel = (ssel[t] != 0) && m;
        const float pv = sel ? spseudo[t] : 0.f;
        pseudo_o[rowo + t] = pv;
        contrib = -pv * lgt;
    }
    red[t] = contrib; __syncthreads();
    for (int s = 128; s > 0; s >>= 1) { if (t < s) red[t] += red[t+s]; __syncthreads(); }
    if (t == 0) {
        atomicAdd(&g_loss_num, red[0]);
        if (sel) atomicAdd(&g_phrase_cnt, 1.f);   // thread 0 holds k==0
    }
    __syncthreads();

    // conf = softmax(logit_m), zero where masked; argmax (tie -> lower idx)
    red[t] = lg; __syncthreads();
    for (int s = 128; s > 0; s >>= 1) { if (t < s) red[t] = fmaxf(red[t], red[t+s]); __syncthreads(); }
    const float mmax = red[0]; __syncthreads();
    float ev = (t < KD && lg > -FLT_MAX) ? __expf(lg - mmax) : 0.f;
    red[t] = ev; __syncthreads();
    for (int s = 128; s > 0; s >>= 1) { if (t < s) red[t] += red[t+s]; __syncthreads(); }
    const float denom = red[0]; __syncthreads();
    if (t < KD) conf_o[rowo + t] = m ? (ev / denom) : 0.f;

    red[t] = (t < KD && m) ? ev : -FLT_MAX; ri[t] = t;
    __syncthreads();
    for (int s = 128; s > 0; s >>= 1) {
        if (t < s) {
            if (red[t+s] > red[t] || (red[t+s] == red[t] && ri[t+s] < ri[t])) {
                red[t] = red[t+s]; ri[t] = ri[t+s];
            }
        }
        __syncthreads();
    }
    const int harg = ri[0];

    // ---- EMA rewrite of this block's scattered row (last occurrence wins;
    //      copy blocks skip these rows via bitmap -> no write race) ----
    if (g_is_last[i] && t < KD) {
        const float h = (t == harg && m) ? 1.f : 0.f;
        newc[crow + t] = EMA * rawc + (1.f - EMA) * h;
    }

    __syncthreads();
    if (t == 0 && atomicAdd(&g_done, 1) == GRID - 1) {
        const float ln = atomicAdd(&g_loss_num, 0.f);
        const float pc = atomicAdd(&g_phrase_cnt, 0.f);
        out[0] = ln / (pc + 1.1920929e-07f);
    }
}

extern "C" void kernel_launch(void* const* d_in, const int* in_sizes, int n_in,
                              void* d_out, int out_size) {
    // Bind inputs by element count (all sizes distinct) -> order-proof.
    const float* outp = nullptr;
    const float* confid = nullptr;
    const int*   braw = nullptr;
    const unsigned char* xmask = nullptr;
    const int*   topkp = nullptr;
    for (int idx = 0; idx < n_in; ++idx) {
        const size_t sz = (size_t)in_sizes[idx];
        if      (sz == N_OUT)  outp   = (const float*)d_in[idx];
        else if (sz == N_CONF) confid = (const float*)d_in[idx];
        else if (sz == (size_t)B) braw = (const int*)d_in[idx];
        else if (sz == N_MASK) xmask  = (const unsigned char*)d_in[idx];
        else if (sz == 1)      topkp  = (const int*)d_in[idx];
    }
    float* out = (float*)d_out;

    const size_t ATT = 1;
    const size_t LOG = ATT + N_OUT;
    const size_t PSE = LOG + N_MASK;
    const size_t CNF = PSE + N_MASK;
    const size_t NEW = CNF + N_MASK;

    k_pre<<<1, 256>>>(xmask, braw, topkp, topkp ? 1 : 0);
    k_main<<<GRID, 256>>>(outp, confid, xmask,
                          out + ATT, out + LOG, out + PSE, out + CNF, out + NEW,
                          out);
}